// round 5
// baseline (speedup 1.0000x reference)
#include <cuda_runtime.h>
#include <math.h>

#define NCH 16
#define NB 5
#define MAXN 20000
#define MAXE 640000

// Scratch (allocation-free: __device__ globals)
__device__ int g_counts[MAXN];
__device__ int g_row[MAXN + 1];
__device__ int g_rank[MAXE];
__device__ int g_eids[MAXE];
__device__ float4 g_geoA[MAXE];   // {rb0, rb1, rb2, rb3} at EDGE order (coalesced)
__device__ float4 g_geoB[MAXE];   // {rb4, y0, y1, y2}   at EDGE order (coalesced)

__global__ void k_zero(int n) {
    int i = blockIdx.x * blockDim.x + threadIdx.x;
    if (i < n) g_counts[i] = 0;
}

// One pass over edges: histogram+rank (atomic) AND per-edge geometry,
// written COALESCED at edge order.
__global__ void k_hist_geo(const int* __restrict__ recv,
                           const float* __restrict__ edges, int E) {
    int i = blockIdx.x * blockDim.x + threadIdx.x;
    if (i >= E) return;
    g_rank[i] = atomicAdd(&g_counts[recv[i]], 1);

    float ex = edges[3 * i + 0];
    float ey = edges[3 * i + 1];
    float ez = edges[3 * i + 2];
    float r2 = fmaf(ex, ex, fmaf(ey, ey, ez * ez));
    float r  = sqrtf(r2);
    // rbf_k = exp(-0.7 (r - c_k)^2) = exp(-0.7 r^2) * exp(1.225 r)^k * exp(-0.7 c_k^2)
    float E0 = __expf(-0.7f * r2);
    float t  = __expf(1.225f * r);
    const float K1 = (float)exp(-0.7 * 0.875 * 0.875);
    const float K2 = (float)exp(-0.7 * 1.75  * 1.75);
    const float K3 = (float)exp(-0.7 * 2.625 * 2.625);
    const float K4 = (float)exp(-0.7 * 3.5   * 3.5);
    float p1 = E0 * t, p2 = p1 * t, p3 = p2 * t, p4 = p3 * t;
    const float Y1C = 0.4886025119029199f;

    g_geoA[i] = make_float4(E0, p1 * K1, p2 * K2, p3 * K3);
    g_geoB[i] = make_float4(p4 * K4, Y1C * ey, Y1C * ez, Y1C * ex);
}

// Single-block scan: thread-serial ITEMS + shfl warp scan + warp-totals scan.
__global__ void k_scan(int n) {
    const int T = 1024;
    const int ITEMS = 20;
    int tid = threadIdx.x;
    int lane = tid & 31, wid = tid >> 5;
    int start = tid * ITEMS;

    int loc[ITEMS];
    int sum = 0;
    #pragma unroll
    for (int k = 0; k < ITEMS; k++) {
        int i = start + k;
        int v = (i < n) ? g_counts[i] : 0;
        loc[k] = sum;
        sum += v;
    }
    int s = sum;
    #pragma unroll
    for (int off = 1; off < 32; off <<= 1) {
        int t = __shfl_up_sync(0xffffffffu, s, off);
        if (lane >= off) s += t;
    }
    __shared__ int wsum[32];
    if (lane == 31) wsum[wid] = s;
    __syncthreads();
    if (wid == 0) {
        int w = wsum[lane];
        #pragma unroll
        for (int off = 1; off < 32; off <<= 1) {
            int t = __shfl_up_sync(0xffffffffu, w, off);
            if (lane >= off) w += t;
        }
        wsum[lane] = w;
    }
    __syncthreads();
    int base = (wid > 0 ? wsum[wid - 1] : 0) + (s - sum);
    #pragma unroll
    for (int k = 0; k < ITEMS; k++) {
        int i = start + k;
        if (i < n) g_row[i] = base + loc[k];
    }
    if (tid == T - 1) g_row[n] = wsum[31];
}

// Atomic-free scatter: ONE scattered 4-byte store per edge.
__global__ void k_scatter(const int* __restrict__ recv, int E) {
    int i = blockIdx.x * blockDim.x + threadIdx.x;
    if (i < E) {
        int pos = g_row[recv[i]] + g_rank[i];
        g_eids[pos] = i;
    }
}

// Main gather: one warp per node, lane = (half<<4)|channel, 2 edges/iter.
__global__ void __launch_bounds__(256) k_main(
    const float* __restrict__ nodes0, const float* __restrict__ nodes1,
    const int* __restrict__ senders,
    const float* __restrict__ c00, const float* __restrict__ c01,
    const float* __restrict__ c10, const float* __restrict__ c11,
    const float* __restrict__ w000, const float* __restrict__ w011,
    const float* __restrict__ w101, const float* __restrict__ w110,
    const float* __restrict__ w111,
    float* __restrict__ out0, float* __restrict__ out1, int n_nodes)
{
    int warp = (blockIdx.x * blockDim.x + threadIdx.x) >> 5;
    if (warp >= n_nodes) return;
    int lane = threadIdx.x & 31;
    int c = lane & 15;
    int half = lane >> 4;

    float a00[NB], a01[NB], a10[NB], a11[NB];
    #pragma unroll
    for (int k = 0; k < NB; k++) {
        a00[k] = c00[c * NB + k];
        a01[k] = c01[c * NB + k];
        a10[k] = c10[c * NB + k];
        a11[k] = c11[c * NB + k];
    }
    const float Y00 = 0.28209479177387814f;
    float W000f = w000[c] * Y00;
    float W011  = w011[c];
    float W101f = w101[c] * Y00;
    float W110f = w110[c] * 0.57735026918962576f;  // 1/sqrt(3)
    float W111f = w111[c] * 0.70710678118654752f;  // 1/sqrt(2)

    int rs = g_row[warp];
    int re = g_row[warp + 1];

    float m0a = 0.f, m0b = 0.f;
    float m1a0 = 0.f, m1a1 = 0.f, m1a2 = 0.f;
    float m1b0 = 0.f, m1b1 = 0.f, m1b2 = 0.f;
    float m1c0 = 0.f, m1c1 = 0.f, m1c2 = 0.f;

    #pragma unroll 2
    for (int base = rs; base < re; base += 2) {
        int it = base + half;
        bool valid = (it < re);
        int p = valid ? it : base;
        int e = g_eids[p];                 // broadcast within half-warp
        float4 ga = g_geoA[e];             // broadcast
        float4 gb = g_geoB[e];             // broadcast
        int s = senders[e];                // broadcast

        float rad00 = fmaf(gb.x, a00[4], fmaf(ga.w, a00[3], fmaf(ga.z, a00[2], fmaf(ga.y, a00[1], ga.x * a00[0]))));
        float rad01 = fmaf(gb.x, a01[4], fmaf(ga.w, a01[3], fmaf(ga.z, a01[2], fmaf(ga.y, a01[1], ga.x * a01[0]))));
        float rad10 = fmaf(gb.x, a10[4], fmaf(ga.w, a10[3], fmaf(ga.z, a10[2], fmaf(ga.y, a10[1], ga.x * a10[0]))));
        float rad11 = fmaf(gb.x, a11[4], fmaf(ga.w, a11[3], fmaf(ga.z, a11[2], fmaf(ga.y, a11[1], ga.x * a11[0]))));

        float y0 = gb.y, y1 = gb.z, y2 = gb.w;

        float n0v = nodes0[s * NCH + c];
        const float* n1p = nodes1 + ((size_t)s * NCH + c) * 3;
        float n1x = n1p[0], n1y = n1p[1], n1z = n1p[2];

        if (valid) {
            m0a = fmaf(W000f, n0v * rad00, m0a);
            float dot11 = fmaf(n1x, y0, fmaf(n1y, y1, n1z * y2));
            m0b = fmaf(W110f * rad11, dot11, m0b);
            float t01 = W011 * n0v * rad01;
            m1a0 = fmaf(t01, y0, m1a0);
            m1a1 = fmaf(t01, y1, m1a1);
            m1a2 = fmaf(t01, y2, m1a2);
            float t10 = W101f * rad10;
            m1b0 = fmaf(t10, n1x, m1b0);
            m1b1 = fmaf(t10, n1y, m1b1);
            m1b2 = fmaf(t10, n1z, m1b2);
            float t11 = W111f * rad11;
            m1c0 = fmaf(t11, n1y * y2 - n1z * y1, m1c0);
            m1c1 = fmaf(t11, n1z * y0 - n1x * y2, m1c1);
            m1c2 = fmaf(t11, n1x * y1 - n1y * y0, m1c2);
        }
    }

    const unsigned FULL = 0xffffffffu;
    m0a  += __shfl_xor_sync(FULL, m0a, 16);
    m0b  += __shfl_xor_sync(FULL, m0b, 16);
    m1a0 += __shfl_xor_sync(FULL, m1a0, 16);
    m1a1 += __shfl_xor_sync(FULL, m1a1, 16);
    m1a2 += __shfl_xor_sync(FULL, m1a2, 16);
    m1b0 += __shfl_xor_sync(FULL, m1b0, 16);
    m1b1 += __shfl_xor_sync(FULL, m1b1, 16);
    m1b2 += __shfl_xor_sync(FULL, m1b2, 16);
    m1c0 += __shfl_xor_sync(FULL, m1c0, 16);
    m1c1 += __shfl_xor_sync(FULL, m1c1, 16);
    m1c2 += __shfl_xor_sync(FULL, m1c2, 16);

    if (half == 0) {
        out0[warp * 32 + c]      = m0a;
        out0[warp * 32 + 16 + c] = m0b;
        float* oa = out1 + ((size_t)warp * 48 + c) * 3;
        oa[0] = m1a0; oa[1] = m1a1; oa[2] = m1a2;
        float* ob = out1 + ((size_t)warp * 48 + 16 + c) * 3;
        ob[0] = m1b0; ob[1] = m1b1; ob[2] = m1b2;
        float* oc = out1 + ((size_t)warp * 48 + 32 + c) * 3;
        oc[0] = m1c0; oc[1] = m1c1; oc[2] = m1c2;
    }
}

extern "C" void kernel_launch(void* const* d_in, const int* in_sizes, int n_in,
                              void* d_out, int out_size) {
    const float* coords  = (const float*)d_in[0];
    const float* nodes0  = (const float*)d_in[1];
    const float* nodes1  = (const float*)d_in[2];
    const float* edges   = (const float*)d_in[3];
    const int*   senders = (const int*)d_in[4];
    const int*   recv    = (const int*)d_in[5];
    const float* c00 = (const float*)d_in[6];
    const float* c01 = (const float*)d_in[7];
    const float* c10 = (const float*)d_in[8];
    const float* c11 = (const float*)d_in[9];
    const float* w000 = (const float*)d_in[10];
    const float* w011 = (const float*)d_in[11];
    const float* w101 = (const float*)d_in[12];
    const float* w110 = (const float*)d_in[13];
    const float* w111 = (const float*)d_in[14];
    float* out = (float*)d_out;

    int N = in_sizes[0] / 3;
    int E = in_sizes[3] / 3;

    cudaMemcpyAsync(out, coords, (size_t)3 * N * sizeof(float),
                    cudaMemcpyDeviceToDevice);
    float* out0 = out + (size_t)3 * N;
    float* out1 = out0 + (size_t)32 * N;

    k_zero<<<(N + 255) / 256, 256>>>(N);
    k_hist_geo<<<(E + 255) / 256, 256>>>(recv, edges, E);
    k_scan<<<1, 1024>>>(N);
    k_scatter<<<(E + 255) / 256, 256>>>(recv, E);
    k_main<<<(N * 32 + 255) / 256, 256>>>(nodes0, nodes1, senders,
                                          c00, c01, c10, c11,
                                          w000, w011, w101, w110, w111,
                                          out0, out1, N);
}

// round 6
// speedup vs baseline: 1.7571x; 1.7571x over previous
#include <cuda_runtime.h>
#include <math.h>

#define NCH 16
#define NB 5
#define MAXN 20000
#define MAXE 640000

// Scratch (allocation-free: __device__ globals)
__device__ int g_counts[MAXN];
__device__ int g_row[MAXN + 1];
__device__ int g_rank[MAXE];
__device__ float4 g_rec[MAXE];    // sorted: {ex, ey, ez, sender_bits}

__global__ void k_zero(int n) {
    int i = blockIdx.x * blockDim.x + threadIdx.x;
    if (i < n) g_counts[i] = 0;
}

// Histogram + per-edge rank in one pass.
__global__ void k_hist(const int* __restrict__ recv, int E) {
    int i = blockIdx.x * blockDim.x + threadIdx.x;
    if (i < E) g_rank[i] = atomicAdd(&g_counts[recv[i]], 1);
}

// Single-block scan: thread-serial ITEMS + shfl warp scan + warp-totals scan.
__global__ void k_scan(int n) {
    const int T = 1024;
    const int ITEMS = 20;
    int tid = threadIdx.x;
    int lane = tid & 31, wid = tid >> 5;
    int start = tid * ITEMS;

    int loc[ITEMS];
    int sum = 0;
    #pragma unroll
    for (int k = 0; k < ITEMS; k++) {
        int i = start + k;
        int v = (i < n) ? g_counts[i] : 0;
        loc[k] = sum;
        sum += v;
    }
    int s = sum;
    #pragma unroll
    for (int off = 1; off < 32; off <<= 1) {
        int t = __shfl_up_sync(0xffffffffu, s, off);
        if (lane >= off) s += t;
    }
    __shared__ int wsum[32];
    if (lane == 31) wsum[wid] = s;
    __syncthreads();
    if (wid == 0) {
        int w = wsum[lane];
        #pragma unroll
        for (int off = 1; off < 32; off <<= 1) {
            int t = __shfl_up_sync(0xffffffffu, w, off);
            if (lane >= off) w += t;
        }
        wsum[lane] = w;
    }
    __syncthreads();
    int base = (wid > 0 ? wsum[wid - 1] : 0) + (s - sum);
    #pragma unroll
    for (int k = 0; k < ITEMS; k++) {
        int i = start + k;
        if (i < n) g_row[i] = base + loc[k];
    }
    if (tid == T - 1) g_row[n] = wsum[31];
}

// Atomic-free scatter: ONE scattered 16-byte store per edge.
__global__ void k_scatter(const int* __restrict__ recv,
                          const int* __restrict__ senders,
                          const float* __restrict__ edges, int E) {
    int i = blockIdx.x * blockDim.x + threadIdx.x;
    if (i >= E) return;
    int pos = g_row[recv[i]] + g_rank[i];
    float ex = edges[3 * i + 0];
    float ey = edges[3 * i + 1];
    float ez = edges[3 * i + 2];
    g_rec[pos] = make_float4(ex, ey, ez, __int_as_float(senders[i]));
}

// Main gather: one warp per node, lane = (half<<4)|channel, 2 edges/iter.
// Sorted records read sequentially; geometry recomputed inline.
__global__ void __launch_bounds__(256) k_main(
    const float* __restrict__ nodes0, const float* __restrict__ nodes1,
    const float* __restrict__ c00, const float* __restrict__ c01,
    const float* __restrict__ c10, const float* __restrict__ c11,
    const float* __restrict__ w000, const float* __restrict__ w011,
    const float* __restrict__ w101, const float* __restrict__ w110,
    const float* __restrict__ w111,
    float* __restrict__ out0, float* __restrict__ out1, int n_nodes)
{
    int warp = (blockIdx.x * blockDim.x + threadIdx.x) >> 5;
    if (warp >= n_nodes) return;
    int lane = threadIdx.x & 31;
    int c = lane & 15;
    int half = lane >> 4;

    float a00[NB], a01[NB], a10[NB], a11[NB];
    #pragma unroll
    for (int k = 0; k < NB; k++) {
        a00[k] = c00[c * NB + k];
        a01[k] = c01[c * NB + k];
        a10[k] = c10[c * NB + k];
        a11[k] = c11[c * NB + k];
    }
    const float Y00 = 0.28209479177387814f;
    float W000f = w000[c] * Y00;
    float W011  = w011[c];
    float W101f = w101[c] * Y00;
    float W110f = w110[c] * 0.57735026918962576f;  // 1/sqrt(3)
    float W111f = w111[c] * 0.70710678118654752f;  // 1/sqrt(2)

    const float K1 = (float)exp(-0.7 * 0.875 * 0.875);
    const float K2 = (float)exp(-0.7 * 1.75  * 1.75);
    const float K3 = (float)exp(-0.7 * 2.625 * 2.625);
    const float K4 = (float)exp(-0.7 * 3.5   * 3.5);
    const float Y1C = 0.4886025119029199f;

    int rs = g_row[warp];
    int re = g_row[warp + 1];

    float m0a = 0.f, m0b = 0.f;
    float m1a0 = 0.f, m1a1 = 0.f, m1a2 = 0.f;
    float m1b0 = 0.f, m1b1 = 0.f, m1b2 = 0.f;
    float m1c0 = 0.f, m1c1 = 0.f, m1c2 = 0.f;

    for (int base = rs; base < re; base += 2) {
        int it = base + half;
        bool valid = (it < re);
        int p = valid ? it : base;
        float4 rec = g_rec[p];             // sequential within warp
        int s = __float_as_int(rec.w);

        float ex = rec.x, ey = rec.y, ez = rec.z;
        float r2 = fmaf(ex, ex, fmaf(ey, ey, ez * ez));
        float r  = sqrtf(r2);
        float E0 = __expf(-0.7f * r2);
        float t  = __expf(1.225f * r);
        float p1 = E0 * t, p2 = p1 * t, p3 = p2 * t, p4 = p3 * t;
        float rb0 = E0, rb1 = p1 * K1, rb2 = p2 * K2, rb3 = p3 * K3, rb4 = p4 * K4;

        float rad00 = fmaf(rb4, a00[4], fmaf(rb3, a00[3], fmaf(rb2, a00[2], fmaf(rb1, a00[1], rb0 * a00[0]))));
        float rad01 = fmaf(rb4, a01[4], fmaf(rb3, a01[3], fmaf(rb2, a01[2], fmaf(rb1, a01[1], rb0 * a01[0]))));
        float rad10 = fmaf(rb4, a10[4], fmaf(rb3, a10[3], fmaf(rb2, a10[2], fmaf(rb1, a10[1], rb0 * a10[0]))));
        float rad11 = fmaf(rb4, a11[4], fmaf(rb3, a11[3], fmaf(rb2, a11[2], fmaf(rb1, a11[1], rb0 * a11[0]))));

        float y0 = Y1C * ey, y1 = Y1C * ez, y2 = Y1C * ex;

        float n0v = nodes0[s * NCH + c];
        const float* n1p = nodes1 + ((size_t)s * NCH + c) * 3;
        float n1x = n1p[0], n1y = n1p[1], n1z = n1p[2];

        if (valid) {
            m0a = fmaf(W000f, n0v * rad00, m0a);
            float dot11 = fmaf(n1x, y0, fmaf(n1y, y1, n1z * y2));
            m0b = fmaf(W110f * rad11, dot11, m0b);
            float t01 = W011 * n0v * rad01;
            m1a0 = fmaf(t01, y0, m1a0);
            m1a1 = fmaf(t01, y1, m1a1);
            m1a2 = fmaf(t01, y2, m1a2);
            float t10 = W101f * rad10;
            m1b0 = fmaf(t10, n1x, m1b0);
            m1b1 = fmaf(t10, n1y, m1b1);
            m1b2 = fmaf(t10, n1z, m1b2);
            float t11 = W111f * rad11;
            m1c0 = fmaf(t11, n1y * y2 - n1z * y1, m1c0);
            m1c1 = fmaf(t11, n1z * y0 - n1x * y2, m1c1);
            m1c2 = fmaf(t11, n1x * y1 - n1y * y0, m1c2);
        }
    }

    const unsigned FULL = 0xffffffffu;
    m0a  += __shfl_xor_sync(FULL, m0a, 16);
    m0b  += __shfl_xor_sync(FULL, m0b, 16);
    m1a0 += __shfl_xor_sync(FULL, m1a0, 16);
    m1a1 += __shfl_xor_sync(FULL, m1a1, 16);
    m1a2 += __shfl_xor_sync(FULL, m1a2, 16);
    m1b0 += __shfl_xor_sync(FULL, m1b0, 16);
    m1b1 += __shfl_xor_sync(FULL, m1b1, 16);
    m1b2 += __shfl_xor_sync(FULL, m1b2, 16);
    m1c0 += __shfl_xor_sync(FULL, m1c0, 16);
    m1c1 += __shfl_xor_sync(FULL, m1c1, 16);
    m1c2 += __shfl_xor_sync(FULL, m1c2, 16);

    if (half == 0) {
        out0[warp * 32 + c]      = m0a;
        out0[warp * 32 + 16 + c] = m0b;
        float* oa = out1 + ((size_t)warp * 48 + c) * 3;
        oa[0] = m1a0; oa[1] = m1a1; oa[2] = m1a2;
        float* ob = out1 + ((size_t)warp * 48 + 16 + c) * 3;
        ob[0] = m1b0; ob[1] = m1b1; ob[2] = m1b2;
        float* oc = out1 + ((size_t)warp * 48 + 32 + c) * 3;
        oc[0] = m1c0; oc[1] = m1c1; oc[2] = m1c2;
    }
}

extern "C" void kernel_launch(void* const* d_in, const int* in_sizes, int n_in,
                              void* d_out, int out_size) {
    const float* coords  = (const float*)d_in[0];
    const float* nodes0  = (const float*)d_in[1];
    const float* nodes1  = (const float*)d_in[2];
    const float* edges   = (const float*)d_in[3];
    const int*   senders = (const int*)d_in[4];
    const int*   recv    = (const int*)d_in[5];
    const float* c00 = (const float*)d_in[6];
    const float* c01 = (const float*)d_in[7];
    const float* c10 = (const float*)d_in[8];
    const float* c11 = (const float*)d_in[9];
    const float* w000 = (const float*)d_in[10];
    const float* w011 = (const float*)d_in[11];
    const float* w101 = (const float*)d_in[12];
    const float* w110 = (const float*)d_in[13];
    const float* w111 = (const float*)d_in[14];
    float* out = (float*)d_out;

    int N = in_sizes[0] / 3;
    int E = in_sizes[3] / 3;

    cudaMemcpyAsync(out, coords, (size_t)3 * N * sizeof(float),
                    cudaMemcpyDeviceToDevice);
    float* out0 = out + (size_t)3 * N;
    float* out1 = out0 + (size_t)32 * N;

    k_zero<<<(N + 255) / 256, 256>>>(N);
    k_hist<<<(E + 255) / 256, 256>>>(recv, E);
    k_scan<<<1, 1024>>>(N);
    k_scatter<<<(E + 255) / 256, 256>>>(recv, senders, edges, E);
    k_main<<<(N * 32 + 255) / 256, 256>>>(nodes0, nodes1,
                                          c00, c01, c10, c11,
                                          w000, w011, w101, w110, w111,
                                          out0, out1, N);
}

// round 7
// speedup vs baseline: 1.8155x; 1.0333x over previous
#include <cuda_runtime.h>
#include <math.h>

#define NCH 16
#define NB 5
#define MAXN 20000
#define MAXE 640000

// Scratch (allocation-free: __device__ globals; zero-initialized at module load)
__device__ int g_counts[MAXN];
__device__ int g_row[MAXN + 1];
__device__ int g_rank[MAXE];
__device__ float4 g_rec[MAXE];    // sorted: {ex, ey, ez, sender_bits}

// Histogram + per-edge rank in one pass. Requires g_counts == 0 on entry
// (true at load; k_scan re-zeroes after reading each call).
__global__ void k_hist(const int* __restrict__ recv, int E) {
    int i = blockIdx.x * blockDim.x + threadIdx.x;
    if (i < E) g_rank[i] = atomicAdd(&g_counts[recv[i]], 1);
}

// Single-block scan: thread-serial ITEMS + shfl warp scan + warp-totals scan.
// Also re-zeroes g_counts for the next kernel_launch call.
__global__ void k_scan(int n) {
    const int T = 1024;
    const int ITEMS = 20;
    int tid = threadIdx.x;
    int lane = tid & 31, wid = tid >> 5;
    int start = tid * ITEMS;

    int loc[ITEMS];
    int sum = 0;
    #pragma unroll
    for (int k = 0; k < ITEMS; k++) {
        int i = start + k;
        int v = (i < n) ? g_counts[i] : 0;
        loc[k] = sum;
        sum += v;
    }
    int s = sum;
    #pragma unroll
    for (int off = 1; off < 32; off <<= 1) {
        int t = __shfl_up_sync(0xffffffffu, s, off);
        if (lane >= off) s += t;
    }
    __shared__ int wsum[32];
    if (lane == 31) wsum[wid] = s;
    __syncthreads();
    if (wid == 0) {
        int w = wsum[lane];
        #pragma unroll
        for (int off = 1; off < 32; off <<= 1) {
            int t = __shfl_up_sync(0xffffffffu, w, off);
            if (lane >= off) w += t;
        }
        wsum[lane] = w;
    }
    __syncthreads();
    int base = (wid > 0 ? wsum[wid - 1] : 0) + (s - sum);
    #pragma unroll
    for (int k = 0; k < ITEMS; k++) {
        int i = start + k;
        if (i < n) { g_row[i] = base + loc[k]; g_counts[i] = 0; }
    }
    if (tid == T - 1) g_row[n] = wsum[31];
}

// Atomic-free scatter: ONE scattered 16-byte store per edge.
__global__ void k_scatter(const int* __restrict__ recv,
                          const int* __restrict__ senders,
                          const float* __restrict__ edges, int E) {
    int i = blockIdx.x * blockDim.x + threadIdx.x;
    if (i >= E) return;
    int pos = g_row[recv[i]] + g_rank[i];
    float ex = edges[3 * i + 0];
    float ey = edges[3 * i + 1];
    float ez = edges[3 * i + 2];
    g_rec[pos] = make_float4(ex, ey, ez, __int_as_float(senders[i]));
}

// Main gather: one warp per node, lane = (half<<4)|channel.
// Manual unroll x2 (4 edges per warp-iter), recs prefetched at loop top.
__global__ void __launch_bounds__(256, 4) k_main(
    const float* __restrict__ nodes0, const float* __restrict__ nodes1,
    const float* __restrict__ c00, const float* __restrict__ c01,
    const float* __restrict__ c10, const float* __restrict__ c11,
    const float* __restrict__ w000, const float* __restrict__ w011,
    const float* __restrict__ w101, const float* __restrict__ w110,
    const float* __restrict__ w111,
    float* __restrict__ out0, float* __restrict__ out1, int n_nodes)
{
    int warp = (blockIdx.x * blockDim.x + threadIdx.x) >> 5;
    if (warp >= n_nodes) return;
    int lane = threadIdx.x & 31;
    int c = lane & 15;
    int half = lane >> 4;

    // Radial coefficients with RBF constants K_k = exp(-0.7 c_k^2) pre-folded.
    const float Kf[NB] = {
        1.0f,
        (float)exp(-0.7 * 0.875 * 0.875),
        (float)exp(-0.7 * 1.75  * 1.75),
        (float)exp(-0.7 * 2.625 * 2.625),
        (float)exp(-0.7 * 3.5   * 3.5)
    };
    float a00[NB], a01[NB], a10[NB], a11[NB];
    #pragma unroll
    for (int k = 0; k < NB; k++) {
        a00[k] = c00[c * NB + k] * Kf[k];
        a01[k] = c01[c * NB + k] * Kf[k];
        a10[k] = c10[c * NB + k] * Kf[k];
        a11[k] = c11[c * NB + k] * Kf[k];
    }
    const float Y00 = 0.28209479177387814f;
    const float Y1C = 0.4886025119029199f;
    float W000f = w000[c] * Y00;
    float W011f = w011[c] * Y1C;
    float W101f = w101[c] * Y00;
    float W110f = w110[c] * 0.57735026918962576f * Y1C;  // 1/sqrt(3) * Y1C
    float W111f = w111[c] * 0.70710678118654752f * Y1C;  // 1/sqrt(2) * Y1C

    int rs = g_row[warp];
    int re = g_row[warp + 1];

    float m0a = 0.f, m0b = 0.f;
    float m1a0 = 0.f, m1a1 = 0.f, m1a2 = 0.f;
    float m1b0 = 0.f, m1b1 = 0.f, m1b2 = 0.f;
    float m1c0 = 0.f, m1c1 = 0.f, m1c2 = 0.f;

    #pragma unroll 1
    for (int base = rs; base < re; base += 4) {
        int i0 = base + half;
        int i1 = base + 2 + half;
        bool v0 = (i0 < re);
        bool v1 = (i1 < re);
        // Both rec loads in flight before any compute (MLP = 2).
        float4 rec0 = g_rec[v0 ? i0 : rs];
        float4 rec1 = g_rec[v1 ? i1 : rs];

        #pragma unroll
        for (int u = 0; u < 2; u++) {
            float4 rec = u ? rec1 : rec0;
            bool valid = u ? v1 : v0;
            int s = __float_as_int(rec.w);
            float ex = rec.x, ey = rec.y, ez = rec.z;

            float n0v = nodes0[s * NCH + c];
            const float* n1p = nodes1 + ((size_t)s * NCH + c) * 3;
            float n1x = n1p[0], n1y = n1p[1], n1z = n1p[2];

            float r2 = fmaf(ex, ex, fmaf(ey, ey, ez * ez));
            float r  = sqrtf(r2);
            float E0 = __expf(-0.7f * r2);
            float t  = __expf(1.225f * r);
            float p1 = E0 * t, p2 = p1 * t, p3 = p2 * t, p4 = p3 * t;

            float rad00 = fmaf(p4, a00[4], fmaf(p3, a00[3], fmaf(p2, a00[2], fmaf(p1, a00[1], E0 * a00[0]))));
            float rad01 = fmaf(p4, a01[4], fmaf(p3, a01[3], fmaf(p2, a01[2], fmaf(p1, a01[1], E0 * a01[0]))));
            float rad10 = fmaf(p4, a10[4], fmaf(p3, a10[3], fmaf(p2, a10[2], fmaf(p1, a10[1], E0 * a10[0]))));
            float rad11 = fmaf(p4, a11[4], fmaf(p3, a11[3], fmaf(p2, a11[2], fmaf(p1, a11[1], E0 * a11[0]))));

            if (valid) {
                // y vector (raw; Y1C folded into weights), order (ey, ez, ex)
                m0a = fmaf(W000f, n0v * rad00, m0a);
                float dot11 = fmaf(n1x, ey, fmaf(n1y, ez, n1z * ex));
                m0b = fmaf(W110f * rad11, dot11, m0b);
                float t01 = W011f * n0v * rad01;
                m1a0 = fmaf(t01, ey, m1a0);
                m1a1 = fmaf(t01, ez, m1a1);
                m1a2 = fmaf(t01, ex, m1a2);
                float t10 = W101f * rad10;
                m1b0 = fmaf(t10, n1x, m1b0);
                m1b1 = fmaf(t10, n1y, m1b1);
                m1b2 = fmaf(t10, n1z, m1b2);
                float t11 = W111f * rad11;
                m1c0 = fmaf(t11, n1y * ex - n1z * ez, m1c0);
                m1c1 = fmaf(t11, n1z * ey - n1x * ex, m1c1);
                m1c2 = fmaf(t11, n1x * ez - n1y * ey, m1c2);
            }
        }
    }

    const unsigned FULL = 0xffffffffu;
    m0a  += __shfl_xor_sync(FULL, m0a, 16);
    m0b  += __shfl_xor_sync(FULL, m0b, 16);
    m1a0 += __shfl_xor_sync(FULL, m1a0, 16);
    m1a1 += __shfl_xor_sync(FULL, m1a1, 16);
    m1a2 += __shfl_xor_sync(FULL, m1a2, 16);
    m1b0 += __shfl_xor_sync(FULL, m1b0, 16);
    m1b1 += __shfl_xor_sync(FULL, m1b1, 16);
    m1b2 += __shfl_xor_sync(FULL, m1b2, 16);
    m1c0 += __shfl_xor_sync(FULL, m1c0, 16);
    m1c1 += __shfl_xor_sync(FULL, m1c1, 16);
    m1c2 += __shfl_xor_sync(FULL, m1c2, 16);

    if (half == 0) {
        out0[warp * 32 + c]      = m0a;
        out0[warp * 32 + 16 + c] = m0b;
        float* oa = out1 + ((size_t)warp * 48 + c) * 3;
        oa[0] = m1a0; oa[1] = m1a1; oa[2] = m1a2;
        float* ob = out1 + ((size_t)warp * 48 + 16 + c) * 3;
        ob[0] = m1b0; ob[1] = m1b1; ob[2] = m1b2;
        float* oc = out1 + ((size_t)warp * 48 + 32 + c) * 3;
        oc[0] = m1c0; oc[1] = m1c1; oc[2] = m1c2;
    }
}

extern "C" void kernel_launch(void* const* d_in, const int* in_sizes, int n_in,
                              void* d_out, int out_size) {
    const float* coords  = (const float*)d_in[0];
    const float* nodes0  = (const float*)d_in[1];
    const float* nodes1  = (const float*)d_in[2];
    const float* edges   = (const float*)d_in[3];
    const int*   senders = (const int*)d_in[4];
    const int*   recv    = (const int*)d_in[5];
    const float* c00 = (const float*)d_in[6];
    const float* c01 = (const float*)d_in[7];
    const float* c10 = (const float*)d_in[8];
    const float* c11 = (const float*)d_in[9];
    const float* w000 = (const float*)d_in[10];
    const float* w011 = (const float*)d_in[11];
    const float* w101 = (const float*)d_in[12];
    const float* w110 = (const float*)d_in[13];
    const float* w111 = (const float*)d_in[14];
    float* out = (float*)d_out;

    int N = in_sizes[0] / 3;
    int E = in_sizes[3] / 3;

    cudaMemcpyAsync(out, coords, (size_t)3 * N * sizeof(float),
                    cudaMemcpyDeviceToDevice);
    float* out0 = out + (size_t)3 * N;
    float* out1 = out0 + (size_t)32 * N;

    k_hist<<<(E + 255) / 256, 256>>>(recv, E);
    k_scan<<<1, 1024>>>(N);
    k_scatter<<<(E + 255) / 256, 256>>>(recv, senders, edges, E);
    k_main<<<(N * 32 + 255) / 256, 256>>>(nodes0, nodes1,
                                          c00, c01, c10, c11,
                                          w000, w011, w101, w110, w111,
                                          out0, out1, N);
}